// round 7
// baseline (speedup 1.0000x reference)
#include <cuda_runtime.h>

typedef unsigned long long ull;

// ---------------- device scratch (no allocations allowed) ----------------
__device__ float g_gatesA[(size_t)512 * 128 * 4096]; // t in [0,512)   : [t][b][4H]
__device__ float g_gatesB[(size_t)512 * 128 * 4096]; // t in [512,1024)
__device__ float g_y0[(size_t)1024 * 128 * 1024];    // [t][b][h]
__device__ float g_y1[(size_t)1024 * 128 * 1024];
__device__ float g_htd[2][1024 * 256];               // h duplicated: [k][b dup pairs]
__device__ float g_hT[128 * 1024];                   // final hidden, [b][h]
__device__ float g_z1[128 * 512];
__device__ float g_z2[128 * 256];

__device__ unsigned g_bar_cnt = 0;
__device__ volatile unsigned g_bar_gen = 0;

// ---------------- helpers ----------------
__device__ __forceinline__ ull pk(float a, float b) {
    ull r; asm("mov.b64 %0,{%1,%2};" : "=l"(r) : "f"(a), "f"(b)); return r;
}
__device__ __forceinline__ void unpk(ull v, float& a, float& b) {
    asm("mov.b64 {%0,%1},%2;" : "=f"(a), "=f"(b) : "l"(v));
}
__device__ __forceinline__ ull f2fma(ull a, ull b, ull c) {
    ull d; asm("fma.rn.f32x2 %0,%1,%2,%3;" : "=l"(d) : "l"(a), "l"(b), "l"(c)); return d;
}
__device__ __forceinline__ float sigm(float x) {
    return __fdividef(1.f, 1.f + __expf(-x));
}
__device__ __forceinline__ float tanh_(float x) {
    return 1.f - __fdividef(2.f, 1.f + __expf(2.f * x));
}

// grid-wide barrier: all 128 blocks co-resident (grid must be 128)
__device__ __forceinline__ void grid_bar() {
    __threadfence();   // make this thread's prior global writes visible
    __syncthreads();
    if (threadIdx.x == 0) {
        unsigned g = g_bar_gen;
        unsigned a = atomicAdd(&g_bar_cnt, 1u);
        if (a == 127u) {
            g_bar_cnt = 0u;
            __threadfence();
            g_bar_gen = g + 1u;
        } else {
            while (g_bar_gen == g) { __nanosleep(32); }
        }
    }
    __syncthreads();
}

// ---------------- generic C = A @ W^T + b0 (+b1), tiled 64x64x16, f32x2 ----------------
// asel: 0 = Aext layer0 x mapping ([B,T,IN], row m = t*B+b)
//       1 = g_y0, 2 = g_y1, 3 = g_hT, 4 = g_z1   (row-major, lda=K)
// csel: 0 = gates (split halves, ldc=4096), 1 = g_z1 (ldc=512), 2 = g_z2 (ldc=256)
__global__ __launch_bounds__(256) void gemm_tn(
    const float* __restrict__ Aext, const float* __restrict__ W,
    const float* __restrict__ b0, const float* __restrict__ b1,
    int K, int asel, int csel)
{
    __shared__ ull   Asd[16][66];   // A duplicated pairs: [k][m] = {a,a}
    __shared__ float Bs[16][68];    // B natural: [k][n]
    const int tid = threadIdx.x;
    const int tx = tid & 15, ty = tid >> 4;
    const int m0 = blockIdx.y * 64, n0 = blockIdx.x * 64;

    const float* base = Aext;
    if (asel == 1) base = g_y0;
    else if (asel == 2) base = g_y1;
    else if (asel == 3) base = g_hT;
    else if (asel == 4) base = g_z1;

    const int r = tid >> 2, kq = tid & 3;
    const float* arow;
    if (asel == 0) {
        int mg = m0 + r;
        arow = Aext + ((size_t)(mg & 127) * 1024 + (size_t)(mg >> 7)) * 128;
    } else {
        arow = base + (size_t)(m0 + r) * K;
    }
    const float* wrow = W + (size_t)(n0 + r) * K;

    ull acc[4][2];
#pragma unroll
    for (int i = 0; i < 4; i++) { acc[i][0] = 0ull; acc[i][1] = 0ull; }

    const int nkt = K >> 4;
    float4 av = *(const float4*)(arow + kq * 4);
    float4 wv = *(const float4*)(wrow + kq * 4);

    for (int kt = 0; kt < nkt; kt++) {
        Asd[kq * 4 + 0][r] = pk(av.x, av.x);
        Asd[kq * 4 + 1][r] = pk(av.y, av.y);
        Asd[kq * 4 + 2][r] = pk(av.z, av.z);
        Asd[kq * 4 + 3][r] = pk(av.w, av.w);
        Bs[kq * 4 + 0][r] = wv.x; Bs[kq * 4 + 1][r] = wv.y;
        Bs[kq * 4 + 2][r] = wv.z; Bs[kq * 4 + 3][r] = wv.w;
        __syncthreads();
        if (kt + 1 < nkt) {
            av = *(const float4*)(arow + (kt + 1) * 16 + kq * 4);
            wv = *(const float4*)(wrow + (kt + 1) * 16 + kq * 4);
        }
#pragma unroll
        for (int k = 0; k < 16; k++) {
            ulonglong2 bv  = *(const ulonglong2*)&Bs[k][tx * 4];      // {b01, b23}
            ulonglong2 a01 = *(const ulonglong2*)&Asd[k][ty * 4];     // {a0d, a1d}
            ulonglong2 a23 = *(const ulonglong2*)&Asd[k][ty * 4 + 2]; // {a2d, a3d}
            acc[0][0] = f2fma(a01.x, bv.x, acc[0][0]); acc[0][1] = f2fma(a01.x, bv.y, acc[0][1]);
            acc[1][0] = f2fma(a01.y, bv.x, acc[1][0]); acc[1][1] = f2fma(a01.y, bv.y, acc[1][1]);
            acc[2][0] = f2fma(a23.x, bv.x, acc[2][0]); acc[2][1] = f2fma(a23.x, bv.y, acc[2][1]);
            acc[3][0] = f2fma(a23.y, bv.x, acc[3][0]); acc[3][1] = f2fma(a23.y, bv.y, acc[3][1]);
        }
        __syncthreads();
    }

    const int n = n0 + tx * 4;
    float bb[4];
#pragma unroll
    for (int jj = 0; jj < 4; jj++) {
        bb[jj] = b0[n + jj];
        if (b1) bb[jj] += b1[n + jj];
    }
#pragma unroll
    for (int mi = 0; mi < 4; mi++) {
        int m = m0 + ty * 4 + mi;
        float c0, c1, c2, c3;
        unpk(acc[mi][0], c0, c1);
        unpk(acc[mi][1], c2, c3);
        float4 outv = make_float4(c0 + bb[0], c1 + bb[1], c2 + bb[2], c3 + bb[3]);
        float* crow;
        if (csel == 0)      crow = (m < 65536 ? g_gatesA : g_gatesB) + (size_t)(m & 65535) * 4096;
        else if (csel == 1) crow = g_z1 + (size_t)m * 512;
        else                crow = g_z2 + (size_t)m * 256;
        *(float4*)(crow + n) = outv;
    }
}

// ---------------- persistent LSTM layer: 1024 steps in one kernel -------------
// grid = 128 blocks (j-tile of 8), 256 threads, 192KB dynamic smem.
// Thread = (j = tid&7, bg = tid>>3): 4 b x 4 gates x 1 j; acc pairs over GATES.
// h kept duplicated in global g_htd[k][b,b]; tile fill is a raw LDG.128->STS.128 copy.
// Dynamic smem: h dup [2 buf][32 k][256] (64KB) + Whh slice [1024 k][8 j][4 g] (128KB).
// ysel: 0 -> write g_y0, 1 -> write g_y1, 2 -> no y, write g_hT at t==1023.
__global__ __launch_bounds__(256, 1) void lstm_layer(const float* __restrict__ Whh, int ysel)
{
    extern __shared__ float sm[];
    float* __restrict__ h_sm = sm;            // 16384 floats: [buf][k(32)][b dup(256)]
    float* __restrict__ w_sm = sm + 16384;    // 32768 floats: [k][j*4+g] natural

    const int tid = threadIdx.x;
    const int j = tid & 7, bg = tid >> 3;
    const int j0 = blockIdx.x << 3;
    const int jg = j0 + j;
    const int b0 = bg << 2;

    // ---- fill Whh slice once: w_sm[k][jj*4+g] = Whh[g*1024 + j0+jj][k] ----
    for (int idx = tid; idx < 8192; idx += 256) {
        int rg = idx >> 8, k4 = idx & 255;
        int jj = rg >> 2, g = rg & 3;
        float4 v = *(const float4*)(Whh + ((size_t)((g << 10) | (j0 + jj))) * 1024 + (k4 << 2));
        int base = (k4 << 2) * 32 + (jj << 2) + g;
        w_sm[base]      = v.x;
        w_sm[base + 32] = v.y;
        w_sm[base + 64] = v.z;
        w_sm[base + 96] = v.w;
    }
    __syncthreads();

    float cc[4] = {0.f, 0.f, 0.f, 0.f};

    // gates for t=0
    float ga[4][4];
#pragma unroll
    for (int i = 0; i < 4; i++) {
        const float* gb = g_gatesA + (size_t)(b0 + i) * 4096 + jg;
        ga[i][0] = __ldcs(gb);
        ga[i][1] = __ldcs(gb + 1024);
        ga[i][2] = __ldcs(gb + 2048);
        ga[i][3] = __ldcs(gb + 3072);
    }

    for (int t = 0; t < 1024; t++) {
        float ad[4][4]; // recurrent contribution [b_i][gate]
        if (t > 0) {
            const float4* __restrict__ h_in4 = (const float4*)g_htd[t & 1];
            ull acc[4][2]; // [b][gate-pair]
#pragma unroll
            for (int i = 0; i < 4; i++) { acc[i][0] = 0ull; acc[i][1] = 0ull; }

            // prefetch tile 0 (pure copy: 8 float4 per thread)
            float4 hp[8];
#pragma unroll
            for (int r2 = 0; r2 < 8; r2++)
                hp[r2] = __ldcg(h_in4 + tid + 256 * r2);

            for (int kt = 0; kt < 32; kt++) {
                const int bufo = (kt & 1) << 13; // *8192 floats
                float4* hs4 = (float4*)(h_sm + bufo);
#pragma unroll
                for (int r2 = 0; r2 < 8; r2++)
                    hs4[tid + 256 * r2] = hp[r2];
                __syncthreads();
                if (kt + 1 < 32) {
                    const float4* src = h_in4 + (kt + 1) * 2048;
#pragma unroll
                    for (int r2 = 0; r2 < 8; r2++)
                        hp[r2] = __ldcg(src + tid + 256 * r2);
                }
                const float* hb = h_sm + bufo + (b0 << 1);
                const float* wb = w_sm + (kt << 10) + (j << 2);
#pragma unroll 8
                for (int k = 0; k < 32; k++) {
                    ulonglong2 w2  = *(const ulonglong2*)&wb[k * 32];      // {g01, g23}
                    ulonglong2 h01 = *(const ulonglong2*)&hb[k * 256];     // {h0d, h1d}
                    ulonglong2 h23 = *(const ulonglong2*)&hb[k * 256 + 4]; // {h2d, h3d}
                    acc[0][0] = f2fma(h01.x, w2.x, acc[0][0]); acc[0][1] = f2fma(h01.x, w2.y, acc[0][1]);
                    acc[1][0] = f2fma(h01.y, w2.x, acc[1][0]); acc[1][1] = f2fma(h01.y, w2.y, acc[1][1]);
                    acc[2][0] = f2fma(h23.x, w2.x, acc[2][0]); acc[2][1] = f2fma(h23.x, w2.y, acc[2][1]);
                    acc[3][0] = f2fma(h23.y, w2.x, acc[3][0]); acc[3][1] = f2fma(h23.y, w2.y, acc[3][1]);
                }
                // no second sync needed: next iteration writes the other buffer,
                // and its post-store sync orders reuse of this one.
            }
#pragma unroll
            for (int i = 0; i < 4; i++) {
                unpk(acc[i][0], ad[i][0], ad[i][1]);
                unpk(acc[i][1], ad[i][2], ad[i][3]);
            }
        } else {
#pragma unroll
            for (int i = 0; i < 4; i++)
#pragma unroll
                for (int g = 0; g < 4; g++) ad[i][g] = 0.f;
        }

        // epilogue: activations + state update (c lives in registers)
        float hv[4];
#pragma unroll
        for (int i = 0; i < 4; i++) {
            float xi = ga[i][0] + ad[i][0];
            float xf = ga[i][1] + ad[i][1];
            float xg = ga[i][2] + ad[i][2];
            float xo = ga[i][3] + ad[i][3];
            float ii = sigm(xi), ff = sigm(xf), gg = tanh_(xg), oo = sigm(xo);
            cc[i] = ff * cc[i] + ii * gg;
            hv[i] = oo * tanh_(cc[i]);
        }
        // h(t+1) input, duplicated transposed layout [k=jg][b dup]
        {
            float* hd = g_htd[(t & 1) ^ 1] + (size_t)jg * 256 + (b0 << 1);
            *(float4*)(hd)     = make_float4(hv[0], hv[0], hv[1], hv[1]);
            *(float4*)(hd + 4) = make_float4(hv[2], hv[2], hv[3], hv[3]);
        }
        if (ysel == 0) {
#pragma unroll
            for (int i = 0; i < 4; i++)
                g_y0[((size_t)t * 128 + b0 + i) * 1024 + jg] = hv[i];
        } else if (ysel == 1) {
#pragma unroll
            for (int i = 0; i < 4; i++)
                g_y1[((size_t)t * 128 + b0 + i) * 1024 + jg] = hv[i];
        } else if (t == 1023) {
#pragma unroll
            for (int i = 0; i < 4; i++)
                g_hT[(size_t)(b0 + i) * 1024 + jg] = hv[i];
        }

        // prefetch next step's gate pre-activations before the barrier
        float gan[4][4];
        if (t < 1023) {
            const float* gp =
                (t + 1 < 512 ? g_gatesA : g_gatesB) + (size_t)((t + 1) & 511) * (128 * 4096);
#pragma unroll
            for (int i = 0; i < 4; i++) {
                const float* gb = gp + (size_t)(b0 + i) * 4096 + jg;
                gan[i][0] = __ldcs(gb);
                gan[i][1] = __ldcs(gb + 1024);
                gan[i][2] = __ldcs(gb + 2048);
                gan[i][3] = __ldcs(gb + 3072);
            }
        }

        grid_bar();

#pragma unroll
        for (int i = 0; i < 4; i++)
#pragma unroll
            for (int g = 0; g < 4; g++) ga[i][g] = gan[i][g];
    }
}

// ---------------- BN (eval) + ReLU, in place on g_z1/g_z2 ----------------
__global__ void bn_relu(int sel, const float* __restrict__ gg, const float* __restrict__ bb,
                        const float* __restrict__ mm, const float* __restrict__ vv, int N)
{
    int idx = blockIdx.x * blockDim.x + threadIdx.x;
    if (idx < 128 * N) {
        int n = idx % N;
        float* Z = (sel == 1) ? g_z1 : g_z2;
        float x = Z[idx];
        x = (x - mm[n]) * rsqrtf(vv[n] + 1e-5f) * gg[n] + bb[n];
        Z[idx] = fmaxf(x, 0.f);
    }
}

// ---------------- final fc3 ----------------
__global__ void fc3_k(const float* __restrict__ W, const float* __restrict__ bias,
                      float* __restrict__ out)
{
    int n = blockIdx.x;     // 0..27
    int b = threadIdx.x;    // 0..127
    const float* z = g_z2 + b * 256;
    const float* w = W + n * 256;
    float acc = 0.f;
#pragma unroll 8
    for (int k = 0; k < 256; k += 4) {
        float4 zv = *(const float4*)(z + k);
        float4 wv = *(const float4*)(w + k);
        acc += zv.x * wv.x + zv.y * wv.y + zv.z * wv.z + zv.w * wv.w;
    }
    out[b * 28 + n] = acc + bias[n];
}

// ---------------- launch ----------------
extern "C" void kernel_launch(void* const* d_in, const int* in_sizes, int n_in,
                              void* d_out, int out_size)
{
    const float* x = (const float*)d_in[0];
    const float* Wih[3] = {(const float*)d_in[1], (const float*)d_in[5], (const float*)d_in[9]};
    const float* Whh[3] = {(const float*)d_in[2], (const float*)d_in[6], (const float*)d_in[10]};
    const float* bih[3] = {(const float*)d_in[3], (const float*)d_in[7], (const float*)d_in[11]};
    const float* bhh[3] = {(const float*)d_in[4], (const float*)d_in[8], (const float*)d_in[12]};
    const float* fc1_w = (const float*)d_in[13]; const float* fc1_b = (const float*)d_in[14];
    const float* bn1_g = (const float*)d_in[15]; const float* bn1_b = (const float*)d_in[16];
    const float* bn1_m = (const float*)d_in[17]; const float* bn1_v = (const float*)d_in[18];
    const float* fc2_w = (const float*)d_in[19]; const float* fc2_b = (const float*)d_in[20];
    const float* bn2_g = (const float*)d_in[21]; const float* bn2_b = (const float*)d_in[22];
    const float* bn2_m = (const float*)d_in[23]; const float* bn2_v = (const float*)d_in[24];
    const float* fc3_w = (const float*)d_in[25]; const float* fc3_b = (const float*)d_in[26];

    const int LSTM_SMEM = 49152 * sizeof(float); // 192 KB dynamic
    static int attr_done = 0;
    if (!attr_done) {
        cudaFuncSetAttribute(lstm_layer, cudaFuncAttributeMaxDynamicSharedMemorySize,
                             LSTM_SMEM);
        attr_done = 1;
    }

    for (int l = 0; l < 3; l++) {
        int K = (l == 0) ? 128 : 1024;
        int asel = (l == 0) ? 0 : ((l == 1) ? 1 : 2);
        gemm_tn<<<dim3(64, 2048), 256>>>((l == 0) ? x : nullptr, Wih[l], bih[l], bhh[l],
                                         K, asel, 0);
        int ysel = (l == 0) ? 0 : ((l == 1) ? 1 : 2);
        lstm_layer<<<128, 256, LSTM_SMEM>>>(Whh[l], ysel);
    }

    // head: final hidden of layer 2 is in g_hT
    gemm_tn<<<dim3(8, 2), 256>>>(nullptr, fc1_w, fc1_b, nullptr, 1024, 3, 1);
    bn_relu<<<256, 256>>>(1, bn1_g, bn1_b, bn1_m, bn1_v, 512);
    gemm_tn<<<dim3(4, 2), 256>>>(nullptr, fc2_w, fc2_b, nullptr, 512, 4, 2);
    bn_relu<<<128, 256>>>(2, bn2_g, bn2_b, bn2_m, bn2_v, 256);
    fc3_k<<<28, 128>>>(fc3_w, fc3_b, (float*)d_out);
}

// round 11
// speedup vs baseline: 1.4495x; 1.4495x over previous
#include <cuda_runtime.h>
#include <cuda_bf16.h>
#include <cstdint>

typedef unsigned long long ull;

// ---------------- device scratch (no allocations allowed) ----------------
__device__ float g_gatesA[(size_t)512 * 128 * 4096]; // t in [0,512)   : [t][b][4H]
__device__ float g_gatesB[(size_t)512 * 128 * 4096]; // t in [512,1024)
__device__ float g_y0[(size_t)1024 * 128 * 1024];    // [t][b][h]
__device__ float g_y1[(size_t)1024 * 128 * 1024];
__device__ __align__(16) __nv_bfloat16 g_hhi[2][128 * 1024]; // h hi [b][k'] (k' permuted)
__device__ __align__(16) __nv_bfloat16 g_hlo[2][128 * 1024]; // h lo [b][k']
__device__ float g_hT[128 * 1024];                   // final hidden, [b][h] (original layout)
__device__ float g_z1[128 * 512];
__device__ float g_z2[128 * 256];

__device__ unsigned g_bar_cnt = 0;
__device__ volatile unsigned g_bar_gen = 0;

// ---------------- helpers ----------------
__device__ __forceinline__ ull pk(float a, float b) {
    ull r; asm("mov.b64 %0,{%1,%2};" : "=l"(r) : "f"(a), "f"(b)); return r;
}
__device__ __forceinline__ void unpk(ull v, float& a, float& b) {
    asm("mov.b64 {%0,%1},%2;" : "=f"(a), "=f"(b) : "l"(v));
}
__device__ __forceinline__ ull f2fma(ull a, ull b, ull c) {
    ull d; asm("fma.rn.f32x2 %0,%1,%2,%3;" : "=l"(d) : "l"(a), "l"(b), "l"(c)); return d;
}
__device__ __forceinline__ float sigm(float x) {
    return __fdividef(1.f, 1.f + __expf(-x));
}
__device__ __forceinline__ float tanh_(float x) {
    return 1.f - __fdividef(2.f, 1.f + __expf(2.f * x));
}

// grid-wide barrier: all 128 blocks co-resident (grid must be 128)
__device__ __forceinline__ void grid_bar() {
    __threadfence();
    __syncthreads();
    if (threadIdx.x == 0) {
        unsigned g = g_bar_gen;
        unsigned a = atomicAdd(&g_bar_cnt, 1u);
        if (a == 127u) {
            g_bar_cnt = 0u;
            __threadfence();
            g_bar_gen = g + 1u;
        } else {
            while (g_bar_gen == g) { __nanosleep(32); }
        }
    }
    __syncthreads();
}

// ---------------- warp MMA primitives (sm_80-era PTX, valid on compute_103) ----------------
__device__ __forceinline__ uint32_t s2u(const void* p) {
    uint32_t a;
    asm("{ .reg .u64 t; cvta.to.shared.u64 t, %1; cvt.u32.u64 %0, t; }" : "=r"(a) : "l"(p));
    return a;
}
__device__ __forceinline__ void ldm4(unsigned* r, uint32_t addr) {
    asm volatile("ldmatrix.sync.aligned.m8n8.x4.shared.b16 {%0,%1,%2,%3}, [%4];"
                 : "=r"(r[0]), "=r"(r[1]), "=r"(r[2]), "=r"(r[3]) : "r"(addr));
}
__device__ __forceinline__ void mma16816(float* c, const unsigned* a, unsigned b0, unsigned b1) {
    asm volatile(
        "mma.sync.aligned.m16n8k16.row.col.f32.bf16.bf16.f32 "
        "{%0,%1,%2,%3}, {%4,%5,%6,%7}, {%8,%9}, {%0,%1,%2,%3};"
        : "+f"(c[0]), "+f"(c[1]), "+f"(c[2]), "+f"(c[3])
        : "r"(a[0]), "r"(a[1]), "r"(a[2]), "r"(a[3]), "r"(b0), "r"(b1));
}

// smem layout (bytes) for lstm_layer_mma:
//  W hi: [32 n][1032 k] bf16 @0      (66048)
//  W lo:                     @66048  (66048)
//  A tiles (h): [128 m][72 k] bf16, 2 bufs x {hi,lo}:
//    buf*36864 + part*18432 @132096  (73728)
#define WHI_OFF  0u
#define WLO_OFF  66048u
#define A_OFF    132096u
#define A_BUF    36864u
#define A_PART   18432u
#define SMEM_MMA 205824

// ---------------- persistent tensor-core (HMMA) LSTM layer ----------------
// grid = 128 blocks (8 j each -> N=32 cols packed n=(jj<<2)|g), 256 threads.
// D[b=128][n=32] = h[b][1024] @ Wpk[n][1024]^T via bf16-split (3 mma products).
// h global storage is column-permuted within each block's 8 j: c=(jj>>1)|((jj&1)<<2);
// the W fill decodes the permutation so A-tiles / W share the same k' axis.
__global__ __launch_bounds__(256, 1) void lstm_layer_mma(const float* __restrict__ Whh, int ysel)
{
    extern __shared__ char smem[];
    const uint32_t sbase = s2u(smem);
    const int tid = threadIdx.x;
    const int w = tid >> 5, l = tid & 31;
    const int tq = l & 3;
    const int r = (w << 4) + (l >> 2);     // base m-row of this thread
    const int j0 = blockIdx.x << 3;

    // ---- fill Whh hi/lo slice: w[n][kp] with kp the permuted k axis ----
    for (int idx = tid; idx < 32768; idx += 256) {
        int n = idx >> 10, kp = idx & 1023;
        int blk = kp >> 3, c = kp & 7;
        int ko = (blk << 3) | ((c & 3) << 1) | (c >> 2);
        int jj = n >> 2, g = n & 3;
        float v = Whh[((size_t)((g << 10) | (j0 + jj))) * 1024 + ko];
        __nv_bfloat16 hi = __float2bfloat16(v);
        __nv_bfloat16 lo = __float2bfloat16(v - __bfloat162float(hi));
        ((__nv_bfloat16*)(smem + WHI_OFF))[n * 1032 + kp] = hi;
        ((__nv_bfloat16*)(smem + WLO_OFF))[n * 1032 + kp] = lo;
    }
    __syncthreads();

    // ldmatrix lane address offsets
    const int mat = l >> 3;
    const int arow = (l & 7) + ((mat & 1) << 3);
    const int akof = (mat >> 1) << 3;
    const uint32_t aoff = (uint32_t)(((w << 4) + arow) * 144 + (akof << 1));
    const int brow = (l & 7) + ((mat >> 1) << 3);
    const int bkof = (mat & 1) << 3;
    uint32_t boff[2];
#pragma unroll
    for (int p = 0; p < 2; p++)
        boff[p] = (uint32_t)(((p << 4) + brow) * 2064 + (bkof << 1));

    const int kb = (tq & 1) ? 2 : 0;   // kept nt pair base
    const int sb = (tq & 1) ? 0 : 2;   // sent nt pair base
    const int dlt = tq >> 1;           // jj parity offset

    float ccr[2][2] = {{0.f, 0.f}, {0.f, 0.f}};  // c state [m][rho]

    // gates for t=0
    float ga[2][2][4];
#pragma unroll
    for (int m = 0; m < 2; m++) {
        int jj = 2 * (kb + m) + dlt;
#pragma unroll
        for (int rho = 0; rho < 2; rho++) {
            const float* gp = g_gatesA + (size_t)(r + 8 * rho) * 4096 + j0 + jj;
#pragma unroll
            for (int g = 0; g < 4; g++) ga[m][rho][g] = __ldcs(gp + (g << 10));
        }
    }

    for (int t = 0; t < 1024; t++) {
        float acc[4][4];
#pragma unroll
        for (int i = 0; i < 4; i++)
#pragma unroll
            for (int e = 0; e < 4; e++) acc[i][e] = 0.f;

        if (t > 0) {
            const uint4* __restrict__ Hh = (const uint4*)g_hhi[t & 1];
            const uint4* __restrict__ Hl = (const uint4*)g_hlo[t & 1];
            const int lrow = tid >> 1;
            const int lq = (tid & 1) << 2;

            uint4 rh[4], rl[4];
#pragma unroll
            for (int i = 0; i < 4; i++) {
                rh[i] = __ldcg(Hh + lrow * 128 + lq + i);
                rl[i] = __ldcg(Hl + lrow * 128 + lq + i);
            }
            // store chunk 0 -> buf 0
#pragma unroll
            for (int i = 0; i < 4; i++) {
                uint32_t so = (uint32_t)(lrow * 144 + (lq + i) * 16);
                *(uint4*)(smem + A_OFF + so) = rh[i];
                *(uint4*)(smem + A_OFF + A_PART + so) = rl[i];
            }
            __syncthreads();

            for (int ct = 0; ct < 16; ct++) {
                const int buf = ct & 1;
                if (ct < 15) {
                    int goff = lrow * 128 + (ct + 1) * 8 + lq;
#pragma unroll
                    for (int i = 0; i < 4; i++) {
                        rh[i] = __ldcg(Hh + goff + i);
                        rl[i] = __ldcg(Hl + goff + i);
                    }
                }
                const uint32_t ah_base = sbase + A_OFF + buf * A_BUF + aoff;
                const uint32_t al_base = ah_base + A_PART;
#pragma unroll
                for (int ks = 0; ks < 4; ks++) {
                    unsigned ah[4], al[4], bh[2][4], bl[2][4];
                    ldm4(ah, ah_base + (ks << 5));
                    ldm4(al, al_base + (ks << 5));
                    const uint32_t kbyte = (uint32_t)((ct << 7) + (ks << 5));
#pragma unroll
                    for (int p = 0; p < 2; p++) {
                        ldm4(bh[p], sbase + WHI_OFF + boff[p] + kbyte);
                        ldm4(bl[p], sbase + WLO_OFF + boff[p] + kbyte);
                    }
#pragma unroll
                    for (int p = 0; p < 2; p++) {
                        mma16816(acc[2 * p],     ah, bh[p][0], bh[p][1]);
                        mma16816(acc[2 * p],     ah, bl[p][0], bl[p][1]);
                        mma16816(acc[2 * p],     al, bh[p][0], bh[p][1]);
                        mma16816(acc[2 * p + 1], ah, bh[p][2], bh[p][3]);
                        mma16816(acc[2 * p + 1], ah, bl[p][2], bl[p][3]);
                        mma16816(acc[2 * p + 1], al, bh[p][2], bh[p][3]);
                    }
                }
                if (ct < 15) {
#pragma unroll
                    for (int i = 0; i < 4; i++) {
                        uint32_t so = (uint32_t)((buf ^ 1) * A_BUF + lrow * 144 + (lq + i) * 16);
                        *(uint4*)(smem + A_OFF + so) = rh[i];
                        *(uint4*)(smem + A_OFF + A_PART + so) = rl[i];
                    }
                    __syncthreads();
                }
            }
        }

        // ---- epilogue: exchange gate-pairs with lane^1, full cells per lane ----
        float own[2][4], oth[2][4];
#pragma unroll
        for (int m = 0; m < 2; m++)
#pragma unroll
            for (int e = 0; e < 4; e++) {
                own[m][e] = acc[kb + m][e];
                oth[m][e] = __shfl_xor_sync(0xffffffffu, acc[sb + m][e], 1);
            }

        float hv[2][2];
#pragma unroll
        for (int m = 0; m < 2; m++) {
#pragma unroll
            for (int rho = 0; rho < 2; rho++) {
                float G0, G1, G2, G3;
                if (!(tq & 1)) {
                    G0 = own[m][2 * rho]; G1 = own[m][2 * rho + 1];
                    G2 = oth[m][2 * rho]; G3 = oth[m][2 * rho + 1];
                } else {
                    G0 = oth[m][2 * rho]; G1 = oth[m][2 * rho + 1];
                    G2 = own[m][2 * rho]; G3 = own[m][2 * rho + 1];
                }
                float xi = ga[m][rho][0] + G0;
                float xf = ga[m][rho][1] + G1;
                float xg = ga[m][rho][2] + G2;
                float xo = ga[m][rho][3] + G3;
                float ii = sigm(xi), ff = sigm(xf), gg = tanh_(xg), oo = sigm(xo);
                ccr[m][rho] = ff * ccr[m][rho] + ii * gg;
                hv[m][rho] = oo * tanh_(ccr[m][rho]);
            }
        }

        // ---- h store (permuted columns c0 = 2*tq, coalesced u32) ----
        {
            const int nb = (t & 1) ^ 1;
            const int col = j0 + 2 * tq;
#pragma unroll
            for (int rho = 0; rho < 2; rho++) {
                int b = r + 8 * rho;
                __nv_bfloat16 h0 = __float2bfloat16(hv[0][rho]);
                __nv_bfloat16 h1 = __float2bfloat16(hv[1][rho]);
                __nv_bfloat16 l0 = __float2bfloat16(hv[0][rho] - __bfloat162float(h0));
                __nv_bfloat16 l1 = __float2bfloat16(hv[1][rho] - __bfloat162float(h1));
                unsigned ph = (unsigned)__bfloat16_as_ushort(h0) |
                              ((unsigned)__bfloat16_as_ushort(h1) << 16);
                unsigned pl = (unsigned)__bfloat16_as_ushort(l0) |
                              ((unsigned)__bfloat16_as_ushort(l1) << 16);
                *(unsigned*)((unsigned short*)g_hhi[nb] + (size_t)b * 1024 + col) = ph;
                *(unsigned*)((unsigned short*)g_hlo[nb] + (size_t)b * 1024 + col) = pl;
            }
        }
        // ---- y / hT store (original jj layout) ----
        if (ysel == 0 || ysel == 1) {
            float* yb = (ysel == 0) ? g_y0 : g_y1;
#pragma unroll
            for (int m = 0; m < 2; m++) {
                int jj = 2 * (kb + m) + dlt;
#pragma unroll
                for (int rho = 0; rho < 2; rho++)
                    yb[((size_t)t * 128 + r + 8 * rho) * 1024 + j0 + jj] = hv[m][rho];
            }
        } else if (t == 1023) {
#pragma unroll
            for (int m = 0; m < 2; m++) {
                int jj = 2 * (kb + m) + dlt;
#pragma unroll
                for (int rho = 0; rho < 2; rho++)
                    g_hT[(size_t)(r + 8 * rho) * 1024 + j0 + jj] = hv[m][rho];
            }
        }

        // ---- prefetch next-step gates before barrier ----
        float gan[2][2][4];
        if (t < 1023) {
            const float* gpb = (t + 1 < 512 ? g_gatesA : g_gatesB)
                               + (size_t)((t + 1) & 511) * (128 * 4096);
#pragma unroll
            for (int m = 0; m < 2; m++) {
                int jj = 2 * (kb + m) + dlt;
#pragma unroll
                for (int rho = 0; rho < 2; rho++) {
                    const float* gp = gpb + (size_t)(r + 8 * rho) * 4096 + j0 + jj;
#pragma unroll
                    for (int g = 0; g < 4; g++) gan[m][rho][g] = __ldcs(gp + (g << 10));
                }
            }
        }

        grid_bar();

#pragma unroll
        for (int m = 0; m < 2; m++)
#pragma unroll
            for (int rho = 0; rho < 2; rho++)
#pragma unroll
                for (int g = 0; g < 4; g++) ga[m][rho][g] = gan[m][rho][g];
    }
}

// ---------------- generic C = A @ W^T + b0 (+b1), tiled 64x64x16, f32x2 ----------------
__global__ __launch_bounds__(256) void gemm_tn(
    const float* __restrict__ Aext, const float* __restrict__ W,
    const float* __restrict__ b0, const float* __restrict__ b1,
    int K, int asel, int csel)
{
    __shared__ ull   Asd[16][66];
    __shared__ float Bs[16][68];
    const int tid = threadIdx.x;
    const int tx = tid & 15, ty = tid >> 4;
    const int m0 = blockIdx.y * 64, n0 = blockIdx.x * 64;

    const float* base = Aext;
    if (asel == 1) base = g_y0;
    else if (asel == 2) base = g_y1;
    else if (asel == 3) base = g_hT;
    else if (asel == 4) base = g_z1;

    const int r = tid >> 2, kq = tid & 3;
    const float* arow;
    if (asel == 0) {
        int mg = m0 + r;
        arow = Aext + ((size_t)(mg & 127) * 1024 + (size_t)(mg >> 7)) * 128;
    } else {
        arow = base + (size_t)(m0 + r) * K;
    }
    const float* wrow = W + (size_t)(n0 + r) * K;

    ull acc[4][2];
#pragma unroll
    for (int i = 0; i < 4; i++) { acc[i][0] = 0ull; acc[i][1] = 0ull; }

    const int nkt = K >> 4;
    float4 av = *(const float4*)(arow + kq * 4);
    float4 wv = *(const float4*)(wrow + kq * 4);

    for (int kt = 0; kt < nkt; kt++) {
        Asd[kq * 4 + 0][r] = pk(av.x, av.x);
        Asd[kq * 4 + 1][r] = pk(av.y, av.y);
        Asd[kq * 4 + 2][r] = pk(av.z, av.z);
        Asd[kq * 4 + 3][r] = pk(av.w, av.w);
        Bs[kq * 4 + 0][r] = wv.x; Bs[kq * 4 + 1][r] = wv.y;
        Bs[kq * 4 + 2][r] = wv.z; Bs[kq * 4 + 3][r] = wv.w;
        __syncthreads();
        if (kt + 1 < nkt) {
            av = *(const float4*)(arow + (kt + 1) * 16 + kq * 4);
            wv = *(const float4*)(wrow + (kt + 1) * 16 + kq * 4);
        }
#pragma unroll
        for (int k = 0; k < 16; k++) {
            ulonglong2 bv  = *(const ulonglong2*)&Bs[k][tx * 4];
            ulonglong2 a01 = *(const ulonglong2*)&Asd[k][ty * 4];
            ulonglong2 a23 = *(const ulonglong2*)&Asd[k][ty * 4 + 2];
            acc[0][0] = f2fma(a01.x, bv.x, acc[0][0]); acc[0][1] = f2fma(a01.x, bv.y, acc[0][1]);
            acc[1][0] = f2fma(a01.y, bv.x, acc[1][0]); acc[1][1] = f2fma(a01.y, bv.y, acc[1][1]);
            acc[2][0] = f2fma(a23.x, bv.x, acc[2][0]); acc[2][1] = f2fma(a23.x, bv.y, acc[2][1]);
            acc[3][0] = f2fma(a23.y, bv.x, acc[3][0]); acc[3][1] = f2fma(a23.y, bv.y, acc[3][1]);
        }
        __syncthreads();
    }

    const int n = n0 + tx * 4;
    float bb[4];
#pragma unroll
    for (int jj = 0; jj < 4; jj++) {
        bb[jj] = b0[n + jj];
        if (b1) bb[jj] += b1[n + jj];
    }
#pragma unroll
    for (int mi = 0; mi < 4; mi++) {
        int m = m0 + ty * 4 + mi;
        float c0, c1, c2, c3;
        unpk(acc[mi][0], c0, c1);
        unpk(acc[mi][1], c2, c3);
        float4 outv = make_float4(c0 + bb[0], c1 + bb[1], c2 + bb[2], c3 + bb[3]);
        float* crow;
        if (csel == 0)      crow = (m < 65536 ? g_gatesA : g_gatesB) + (size_t)(m & 65535) * 4096;
        else if (csel == 1) crow = g_z1 + (size_t)m * 512;
        else                crow = g_z2 + (size_t)m * 256;
        *(float4*)(crow + n) = outv;
    }
}

// ---------------- BN (eval) + ReLU, in place on g_z1/g_z2 ----------------
__global__ void bn_relu(int sel, const float* __restrict__ gg, const float* __restrict__ bb,
                        const float* __restrict__ mm, const float* __restrict__ vv, int N)
{
    int idx = blockIdx.x * blockDim.x + threadIdx.x;
    if (idx < 128 * N) {
        int n = idx % N;
        float* Z = (sel == 1) ? g_z1 : g_z2;
        float x = Z[idx];
        x = (x - mm[n]) * rsqrtf(vv[n] + 1e-5f) * gg[n] + bb[n];
        Z[idx] = fmaxf(x, 0.f);
    }
}

// ---------------- final fc3 ----------------
__global__ void fc3_k(const float* __restrict__ W, const float* __restrict__ bias,
                      float* __restrict__ out)
{
    int n = blockIdx.x;
    int b = threadIdx.x;
    const float* z = g_z2 + b * 256;
    const float* w = W + n * 256;
    float acc = 0.f;
#pragma unroll 8
    for (int k = 0; k < 256; k += 4) {
        float4 zv = *(const float4*)(z + k);
        float4 wv = *(const float4*)(w + k);
        acc += zv.x * wv.x + zv.y * wv.y + zv.z * wv.z + zv.w * wv.w;
    }
    out[b * 28 + n] = acc + bias[n];
}

// ---------------- launch ----------------
extern "C" void kernel_launch(void* const* d_in, const int* in_sizes, int n_in,
                              void* d_out, int out_size)
{
    const float* x = (const float*)d_in[0];
    const float* Wih[3] = {(const float*)d_in[1], (const float*)d_in[5], (const float*)d_in[9]};
    const float* Whh[3] = {(const float*)d_in[2], (const float*)d_in[6], (const float*)d_in[10]};
    const float* bih[3] = {(const float*)d_in[3], (const float*)d_in[7], (const float*)d_in[11]};
    const float* bhh[3] = {(const float*)d_in[4], (const float*)d_in[8], (const float*)d_in[12]};
    const float* fc1_w = (const float*)d_in[13]; const float* fc1_b = (const float*)d_in[14];
    const float* bn1_g = (const float*)d_in[15]; const float* bn1_b = (const float*)d_in[16];
    const float* bn1_m = (const float*)d_in[17]; const float* bn1_v = (const float*)d_in[18];
    const float* fc2_w = (const float*)d_in[19]; const float* fc2_b = (const float*)d_in[20];
    const float* bn2_g = (const float*)d_in[21]; const float* bn2_b = (const float*)d_in[22];
    const float* bn2_m = (const float*)d_in[23]; const float* bn2_v = (const float*)d_in[24];
    const float* fc3_w = (const float*)d_in[25]; const float* fc3_b = (const float*)d_in[26];

    static int attr_done = 0;
    if (!attr_done) {
        cudaFuncSetAttribute(lstm_layer_mma, cudaFuncAttributeMaxDynamicSharedMemorySize,
                             SMEM_MMA);
        attr_done = 1;
    }

    for (int l = 0; l < 3; l++) {
        int K = (l == 0) ? 128 : 1024;
        int asel = (l == 0) ? 0 : ((l == 1) ? 1 : 2);
        gemm_tn<<<dim3(64, 2048), 256>>>((l == 0) ? x : nullptr, Wih[l], bih[l], bhh[l],
                                         K, asel, 0);
        int ysel = (l == 0) ? 0 : ((l == 1) ? 1 : 2);
        lstm_layer_mma<<<128, 256, SMEM_MMA>>>(Whh[l], ysel);
    }

    // head: final hidden of layer 2 is in g_hT
    gemm_tn<<<dim3(8, 2), 256>>>(nullptr, fc1_w, fc1_b, nullptr, 1024, 3, 1);
    bn_relu<<<256, 256>>>(1, bn1_g, bn1_b, bn1_m, bn1_v, 512);
    gemm_tn<<<dim3(4, 2), 256>>>(nullptr, fc2_w, fc2_b, nullptr, 512, 4, 2);
    bn_relu<<<128, 256>>>(2, bn2_g, bn2_b, bn2_m, bn2_v, 256);
    fc3_k<<<28, 128>>>(fc3_w, fc3_b, (float*)d_out);
}

// round 14
// speedup vs baseline: 2.1648x; 1.4935x over previous
#include <cuda_runtime.h>
#include <cuda_bf16.h>
#include <cstdint>

typedef unsigned long long ull;

// ---------------- device scratch (no allocations allowed) ----------------
__device__ float g_gatesA[(size_t)512 * 128 * 4096]; // t in [0,512)   : [t][b][4H]
__device__ float g_gatesB[(size_t)512 * 128 * 4096]; // t in [512,1024)
__device__ __align__(16) __nv_bfloat16 g_ybhi[(size_t)131072 * 1024]; // y hi [m][k]
__device__ __align__(16) __nv_bfloat16 g_yblo[(size_t)131072 * 1024]; // y lo [m][k]
__device__ __align__(16) __nv_bfloat16 g_wkhi[(size_t)4096 * 1024];   // Wih hi [n][k]
__device__ __align__(16) __nv_bfloat16 g_wklo[(size_t)4096 * 1024];   // Wih lo [n][k]
__device__ __align__(16) __nv_bfloat16 g_hhi[2][128 * 1024]; // h hi [b][k'] (k' permuted)
__device__ __align__(16) __nv_bfloat16 g_hlo[2][128 * 1024]; // h lo [b][k']
__device__ float g_hT[128 * 1024];                   // final hidden, [b][h]
__device__ float g_z1[128 * 512];
__device__ float g_z2[128 * 256];

__device__ unsigned g_bar_cnt = 0;
__device__ volatile unsigned g_bar_gen = 0;

// ---------------- helpers ----------------
__device__ __forceinline__ ull pk(float a, float b) {
    ull r; asm("mov.b64 %0,{%1,%2};" : "=l"(r) : "f"(a), "f"(b)); return r;
}
__device__ __forceinline__ void unpk(ull v, float& a, float& b) {
    asm("mov.b64 {%0,%1},%2;" : "=f"(a), "=f"(b) : "l"(v));
}
__device__ __forceinline__ ull f2fma(ull a, ull b, ull c) {
    ull d; asm("fma.rn.f32x2 %0,%1,%2,%3;" : "=l"(d) : "l"(a), "l"(b), "l"(c)); return d;
}
__device__ __forceinline__ float sigm(float x) {
    return __fdividef(1.f, 1.f + __expf(-x));
}
__device__ __forceinline__ float tanh_(float x) {
    return 1.f - __fdividef(2.f, 1.f + __expf(2.f * x));
}

// grid-wide barrier: all 128 blocks co-resident (grid must be 128)
__device__ __forceinline__ void grid_bar() {
    __threadfence();
    __syncthreads();
    if (threadIdx.x == 0) {
        unsigned g = g_bar_gen;
        unsigned a = atomicAdd(&g_bar_cnt, 1u);
        if (a == 127u) {
            g_bar_cnt = 0u;
            __threadfence();
            g_bar_gen = g + 1u;
        } else {
            while (g_bar_gen == g) { __nanosleep(32); }
        }
    }
    __syncthreads();
}

// ---------------- warp MMA primitives ----------------
__device__ __forceinline__ uint32_t s2u(const void* p) {
    uint32_t a;
    asm("{ .reg .u64 t; cvta.to.shared.u64 t, %1; cvt.u32.u64 %0, t; }" : "=r"(a) : "l"(p));
    return a;
}
__device__ __forceinline__ void ldm4(unsigned* r, uint32_t addr) {
    asm volatile("ldmatrix.sync.aligned.m8n8.x4.shared.b16 {%0,%1,%2,%3}, [%4];"
                 : "=r"(r[0]), "=r"(r[1]), "=r"(r[2]), "=r"(r[3]) : "r"(addr));
}
__device__ __forceinline__ void mma16816(float* c, const unsigned* a, unsigned b0, unsigned b1) {
    asm volatile(
        "mma.sync.aligned.m16n8k16.row.col.f32.bf16.bf16.f32 "
        "{%0,%1,%2,%3}, {%4,%5,%6,%7}, {%8,%9}, {%0,%1,%2,%3};"
        : "+f"(c[0]), "+f"(c[1]), "+f"(c[2]), "+f"(c[3])
        : "r"(a[0]), "r"(a[1]), "r"(a[2]), "r"(a[3]), "r"(b0), "r"(b1));
}
__device__ __forceinline__ void cpa16(uint32_t s, const void* g) {
    asm volatile("cp.async.cg.shared.global [%0], [%1], 16;" :: "r"(s), "l"(g) : "memory");
}
#define CP_COMMIT() asm volatile("cp.async.commit_group;" ::: "memory")
#define CP_WAIT(n)  asm volatile("cp.async.wait_group %0;" :: "n"(n) : "memory")

// ================= big input-projection GEMM via bf16-split mma =================
// C[m=131072][n=4096] = Yhi/lo[m][1024] @ Whi/lo[n][1024]^T + (b0+b1), gates out.
// Block tile 128m x 128n, K-tile 64, 256 thr (8 warps: warp = m32 x n64).
// smem planes (bytes): A: buf*36864 + part*18432; B: 73728 + buf*36864 + part*18432
#define SMEM_GEMM 147456
__global__ __launch_bounds__(256, 1) void gemm_mma(const float* __restrict__ b0v,
                                                   const float* __restrict__ b1v)
{
    extern __shared__ char sm[];
    const uint32_t sb = s2u(sm);
    const int tid = threadIdx.x;
    const int w = tid >> 5, l = tid & 31;
    const int wm = w & 3, wn = w >> 2;
    const int n0 = blockIdx.x << 7, m0 = blockIdx.y << 7;

    const int mat = l >> 3;
    const int arow = (l & 7) + ((mat & 1) << 3);
    const int akof = (mat >> 1) << 3;
    const int brow = (l & 7) + ((mat >> 1) << 3);
    const int bkof = (mat & 1) << 3;

    float acc[2][8][4];
#pragma unroll
    for (int i = 0; i < 2; i++)
#pragma unroll
        for (int jn = 0; jn < 8; jn++)
#pragma unroll
            for (int e = 0; e < 4; e++) acc[i][jn][e] = 0.f;

    // ---- fill tile t into buf ----
    auto fill = [&](int t, int buf) {
        const int k0 = t << 6;
#pragma unroll
        for (int i = 0; i < 4; i++) {
            int e = tid + (i << 8);
            int row = e >> 3, q = e & 7;
            uint32_t sa = sb + (uint32_t)(buf * 36864 + row * 144 + q * 16);
            const __nv_bfloat16* gh = g_ybhi + (size_t)(m0 + row) * 1024 + k0 + q * 8;
            const __nv_bfloat16* gl = g_yblo + (size_t)(m0 + row) * 1024 + k0 + q * 8;
            cpa16(sa, gh);
            cpa16(sa + 18432u, gl);
            uint32_t sbb = sb + 73728u + (uint32_t)(buf * 36864 + row * 144 + q * 16);
            cpa16(sbb, g_wkhi + (size_t)(n0 + row) * 1024 + k0 + q * 8);
            cpa16(sbb + 18432u, g_wklo + (size_t)(n0 + row) * 1024 + k0 + q * 8);
        }
    };

    fill(0, 0);
    CP_COMMIT();

    for (int t = 0; t < 16; t++) {
        const int buf = t & 1;
        if (t < 15) {
            fill(t + 1, buf ^ 1);
            CP_COMMIT();
            CP_WAIT(1);
        } else {
            CP_WAIT(0);
        }
        __syncthreads();

#pragma unroll
        for (int ks = 0; ks < 4; ks++) {
            unsigned ah[2][4], al[2][4], bh[4][4], bl[4][4];
#pragma unroll
            for (int mt = 0; mt < 2; mt++) {
                uint32_t aa = sb + (uint32_t)(buf * 36864 +
                              (wm * 32 + mt * 16 + arow) * 144 + akof * 2 + ks * 32);
                ldm4(ah[mt], aa);
                ldm4(al[mt], aa + 18432u);
            }
#pragma unroll
            for (int p = 0; p < 4; p++) {
                uint32_t ba = sb + 73728u + (uint32_t)(buf * 36864 +
                              (wn * 64 + p * 16 + brow) * 144 + bkof * 2 + ks * 32);
                ldm4(bh[p], ba);
                ldm4(bl[p], ba + 18432u);
            }
#pragma unroll
            for (int mt = 0; mt < 2; mt++)
#pragma unroll
                for (int p = 0; p < 4; p++) {
                    mma16816(acc[mt][2 * p],     ah[mt], bh[p][0], bh[p][1]);
                    mma16816(acc[mt][2 * p],     ah[mt], bl[p][0], bl[p][1]);
                    mma16816(acc[mt][2 * p],     al[mt], bh[p][0], bh[p][1]);
                    mma16816(acc[mt][2 * p + 1], ah[mt], bh[p][2], bh[p][3]);
                    mma16816(acc[mt][2 * p + 1], ah[mt], bl[p][2], bl[p][3]);
                    mma16816(acc[mt][2 * p + 1], al[mt], bh[p][2], bh[p][3]);
                }
        }
        __syncthreads();
    }

    // ---- epilogue: + (b0+b1), write gates fp32 ----
    float* hbase = (m0 < 65536 ? g_gatesA : g_gatesB);
    const int mh = m0 & 65535;
    const int cbase = n0 + wn * 64 + (l & 3) * 2;
    float bb[8][2];
#pragma unroll
    for (int p = 0; p < 4; p++)
#pragma unroll
        for (int blk = 0; blk < 2; blk++) {
            int col = cbase + p * 16 + blk * 8;
            bb[2 * p + blk][0] = __ldg(b0v + col) + __ldg(b1v + col);
            bb[2 * p + blk][1] = __ldg(b0v + col + 1) + __ldg(b1v + col + 1);
        }
#pragma unroll
    for (int mt = 0; mt < 2; mt++) {
        int r = mh + wm * 32 + mt * 16 + (l >> 2);
        float* rowA = hbase + (size_t)r * 4096;
        float* rowB = rowA + (size_t)8 * 4096;
#pragma unroll
        for (int p = 0; p < 4; p++)
#pragma unroll
            for (int blk = 0; blk < 2; blk++) {
                int col = cbase + p * 16 + blk * 8;
                const float* a4 = acc[mt][2 * p + blk];
                *(float2*)(rowA + col) = make_float2(a4[0] + bb[2 * p + blk][0],
                                                     a4[1] + bb[2 * p + blk][1]);
                *(float2*)(rowB + col) = make_float2(a4[2] + bb[2 * p + blk][0],
                                                     a4[3] + bb[2 * p + blk][1]);
            }
    }
}

// ---------------- Wih fp32 -> bf16 hi/lo pre-convert ----------------
__global__ void wsplit(const float* __restrict__ W) {
    int i = blockIdx.x * 256 + threadIdx.x; // 4M
    float v = W[i];
    __nv_bfloat16 h = __float2bfloat16(v);
    g_wkhi[i] = h;
    g_wklo[i] = __float2bfloat16(v - __bfloat162float(h));
}

// smem layout (bytes) for lstm_layer_mma:
#define WHI_OFF  0u
#define WLO_OFF  66048u
#define A_OFF    132096u
#define A_BUF    36864u
#define A_PART   18432u
#define SMEM_MMA 205824

// ---------------- persistent tensor-core (HMMA) LSTM layer ----------------
// grid = 128 blocks (8 j each -> N=32 cols packed n=(jj<<2)|g), 256 threads.
// ysel: 0/1 -> write y bf16 hi/lo, 2 -> no y, write g_hT fp32 at t==1023.
__global__ __launch_bounds__(256, 1) void lstm_layer_mma(const float* __restrict__ Whh, int ysel)
{
    extern __shared__ char smem[];
    const uint32_t sbase = s2u(smem);
    const int tid = threadIdx.x;
    const int w = tid >> 5, l = tid & 31;
    const int tq = l & 3;
    const int r = (w << 4) + (l >> 2);
    const int j0 = blockIdx.x << 3;

    // ---- fill Whh hi/lo slice: w[n][kp] with kp the permuted k axis ----
    for (int idx = tid; idx < 32768; idx += 256) {
        int n = idx >> 10, kp = idx & 1023;
        int blk = kp >> 3, c = kp & 7;
        int ko = (blk << 3) | ((c & 3) << 1) | (c >> 2);
        int jj = n >> 2, g = n & 3;
        float v = Whh[((size_t)((g << 10) | (j0 + jj))) * 1024 + ko];
        __nv_bfloat16 hi = __float2bfloat16(v);
        __nv_bfloat16 lo = __float2bfloat16(v - __bfloat162float(hi));
        ((__nv_bfloat16*)(smem + WHI_OFF))[n * 1032 + kp] = hi;
        ((__nv_bfloat16*)(smem + WLO_OFF))[n * 1032 + kp] = lo;
    }
    __syncthreads();

    const int mat = l >> 3;
    const int arow = (l & 7) + ((mat & 1) << 3);
    const int akof = (mat >> 1) << 3;
    const uint32_t aoff = (uint32_t)(((w << 4) + arow) * 144 + (akof << 1));
    const int brow = (l & 7) + ((mat >> 1) << 3);
    const int bkof = (mat & 1) << 3;
    uint32_t boff[2];
#pragma unroll
    for (int p = 0; p < 2; p++)
        boff[p] = (uint32_t)(((p << 4) + brow) * 2064 + (bkof << 1));

    const int kb = (tq & 1) ? 2 : 0;
    const int sb2 = (tq & 1) ? 0 : 2;
    const int dlt = tq >> 1;

    float ccr[2][2] = {{0.f, 0.f}, {0.f, 0.f}};

    float ga[2][2][4];
#pragma unroll
    for (int m = 0; m < 2; m++) {
        int jj = 2 * (kb + m) + dlt;
#pragma unroll
        for (int rho = 0; rho < 2; rho++) {
            const float* gp = g_gatesA + (size_t)(r + 8 * rho) * 4096 + j0 + jj;
#pragma unroll
            for (int g = 0; g < 4; g++) ga[m][rho][g] = __ldcs(gp + (g << 10));
        }
    }

    for (int t = 0; t < 1024; t++) {
        float acc[4][4];
#pragma unroll
        for (int i = 0; i < 4; i++)
#pragma unroll
            for (int e = 0; e < 4; e++) acc[i][e] = 0.f;

        if (t > 0) {
            const uint4* __restrict__ Hh = (const uint4*)g_hhi[t & 1];
            const uint4* __restrict__ Hl = (const uint4*)g_hlo[t & 1];
            const int lrow = tid >> 1;
            const int lq = (tid & 1) << 2;

            uint4 rh[4], rl[4];
#pragma unroll
            for (int i = 0; i < 4; i++) {
                rh[i] = __ldcg(Hh + lrow * 128 + lq + i);
                rl[i] = __ldcg(Hl + lrow * 128 + lq + i);
            }
#pragma unroll
            for (int i = 0; i < 4; i++) {
                uint32_t so = (uint32_t)(lrow * 144 + (lq + i) * 16);
                *(uint4*)(smem + A_OFF + so) = rh[i];
                *(uint4*)(smem + A_OFF + A_PART + so) = rl[i];
            }
            __syncthreads();

            for (int ct = 0; ct < 16; ct++) {
                const int buf = ct & 1;
                if (ct < 15) {
                    int goff = lrow * 128 + (ct + 1) * 8 + lq;
#pragma unroll
                    for (int i = 0; i < 4; i++) {
                        rh[i] = __ldcg(Hh + goff + i);
                        rl[i] = __ldcg(Hl + goff + i);
                    }
                }
                const uint32_t ah_base = sbase + A_OFF + buf * A_BUF + aoff;
                const uint32_t al_base = ah_base + A_PART;
#pragma unroll
                for (int ks = 0; ks < 4; ks++) {
                    unsigned ah[4], al[4], bh[2][4], bl[2][4];
                    ldm4(ah, ah_base + (ks << 5));
                    ldm4(al, al_base + (ks << 5));
                    const uint32_t kbyte = (uint32_t)((ct << 7) + (ks << 5));
#pragma unroll
                    for (int p = 0; p < 2; p++) {
                        ldm4(bh[p], sbase + WHI_OFF + boff[p] + kbyte);
                        ldm4(bl[p], sbase + WLO_OFF + boff[p] + kbyte);
                    }
#pragma unroll
                    for (int p = 0; p < 2; p++) {
                        mma16816(acc[2 * p],     ah, bh[p][0], bh[p][1]);
                        mma16816(acc[2 * p],     ah, bl[p][0], bl[p][1]);
                        mma16816(acc[2 * p],     al, bh[p][0], bh[p][1]);
                        mma16816(acc[2 * p + 1], ah, bh[p][2], bh[p][3]);
                        mma16816(acc[2 * p + 1], ah, bl[p][2], bl[p][3]);
                        mma16816(acc[2 * p + 1], al, bh[p][2], bh[p][3]);
                    }
                }
                if (ct < 15) {
#pragma unroll
                    for (int i = 0; i < 4; i++) {
                        uint32_t so = (uint32_t)((buf ^ 1) * A_BUF + lrow * 144 + (lq + i) * 16);
                        *(uint4*)(smem + A_OFF + so) = rh[i];
                        *(uint4*)(smem + A_OFF + A_PART + so) = rl[i];
                    }
                    __syncthreads();
                }
            }
        }

        float own[2][4], oth[2][4];
#pragma unroll
        for (int m = 0; m < 2; m++)
#pragma unroll
            for (int e = 0; e < 4; e++) {
                own[m][e] = acc[kb + m][e];
                oth[m][e] = __shfl_xor_sync(0xffffffffu, acc[sb2 + m][e], 1);
            }

        float hv[2][2];
#pragma unroll
        for (int m = 0; m < 2; m++) {
#pragma unroll
            for (int rho = 0; rho < 2; rho++) {
                float G0, G1, G2, G3;
                if (!(tq & 1)) {
                    G0 = own[m][2 * rho]; G1 = own[m][2 * rho + 1];
                    G2 = oth[m][2 * rho]; G3 = oth[m][2 * rho + 1];
                } else {
                    G0 = oth[m][2 * rho]; G1 = oth[m][2 * rho + 1];
                    G2 = own[m][2 * rho]; G3 = own[m][2 * rho + 1];
                }
                float xi = ga[m][rho][0] + G0;
                float xf = ga[m][rho][1] + G1;
                float xg = ga[m][rho][2] + G2;
                float xo = ga[m][rho][3] + G3;
                float ii = sigm(xi), ff = sigm(xf), gg = tanh_(xg), oo = sigm(xo);
                ccr[m][rho] = ff * ccr[m][rho] + ii * gg;
                hv[m][rho] = oo * tanh_(ccr[m][rho]);
            }
        }

        // ---- h store (permuted columns, coalesced u32) ----
        {
            const int nb = (t & 1) ^ 1;
            const int col = j0 + 2 * tq;
#pragma unroll
            for (int rho = 0; rho < 2; rho++) {
                int b = r + 8 * rho;
                __nv_bfloat16 h0 = __float2bfloat16(hv[0][rho]);
                __nv_bfloat16 h1 = __float2bfloat16(hv[1][rho]);
                __nv_bfloat16 l0 = __float2bfloat16(hv[0][rho] - __bfloat162float(h0));
                __nv_bfloat16 l1 = __float2bfloat16(hv[1][rho] - __bfloat162float(h1));
                unsigned ph = (unsigned)__bfloat16_as_ushort(h0) |
                              ((unsigned)__bfloat16_as_ushort(h1) << 16);
                unsigned pl = (unsigned)__bfloat16_as_ushort(l0) |
                              ((unsigned)__bfloat16_as_ushort(l1) << 16);
                *(unsigned*)((unsigned short*)g_hhi[nb] + (size_t)b * 1024 + col) = ph;
                *(unsigned*)((unsigned short*)g_hlo[nb] + (size_t)b * 1024 + col) = pl;
            }
        }
        // ---- y store as bf16 hi/lo (original jj layout), or hT fp32 ----
        if (ysel != 2) {
#pragma unroll
            for (int m = 0; m < 2; m++) {
                int jj = 2 * (kb + m) + dlt;
#pragma unroll
                for (int rho = 0; rho < 2; rho++) {
                    float v = hv[m][rho];
                    __nv_bfloat16 hh = __float2bfloat16(v);
                    __nv_bfloat16 ll = __float2bfloat16(v - __bfloat162float(hh));
                    size_t off = ((size_t)t * 128 + r + 8 * rho) * 1024 + j0 + jj;
                    g_ybhi[off] = hh;
                    g_yblo[off] = ll;
                }
            }
        } else if (t == 1023) {
#pragma unroll
            for (int m = 0; m < 2; m++) {
                int jj = 2 * (kb + m) + dlt;
#pragma unroll
                for (int rho = 0; rho < 2; rho++)
                    g_hT[(size_t)(r + 8 * rho) * 1024 + j0 + jj] = hv[m][rho];
            }
        }

        float gan[2][2][4];
        if (t < 1023) {
            const float* gpb = (t + 1 < 512 ? g_gatesA : g_gatesB)
                               + (size_t)((t + 1) & 511) * (128 * 4096);
#pragma unroll
            for (int m = 0; m < 2; m++) {
                int jj = 2 * (kb + m) + dlt;
#pragma unroll
                for (int rho = 0; rho < 2; rho++) {
                    const float* gp = gpb + (size_t)(r + 8 * rho) * 4096 + j0 + jj;
#pragma unroll
                    for (int g = 0; g < 4; g++) gan[m][rho][g] = __ldcs(gp + (g << 10));
                }
            }
        }

        grid_bar();

#pragma unroll
        for (int m = 0; m < 2; m++)
#pragma unroll
            for (int rho = 0; rho < 2; rho++)
#pragma unroll
                for (int g = 0; g < 4; g++) ga[m][rho][g] = gan[m][rho][g];
    }
}

// ---------------- generic C = A @ W^T + b0 (+b1), tiled 64x64x16, f32x2 ----------------
// asel: 0 = Aext layer0 x mapping; 3 = g_hT; 4 = g_z1
// csel: 0 = gates, 1 = g_z1, 2 = g_z2
__global__ __launch_bounds__(256) void gemm_tn(
    const float* __restrict__ Aext, const float* __restrict__ W,
    const float* __restrict__ b0, const float* __restrict__ b1,
    int K, int asel, int csel)
{
    __shared__ ull   Asd[16][66];
    __shared__ float Bs[16][68];
    const int tid = threadIdx.x;
    const int tx = tid & 15, ty = tid >> 4;
    const int m0 = blockIdx.y * 64, n0 = blockIdx.x * 64;

    const float* base = Aext;
    if (asel == 3) base = g_hT;
    else if (asel == 4) base = g_z1;

    const int r = tid >> 2, kq = tid & 3;
    const float* arow;
    if (asel == 0) {
        int mg = m0 + r;
        arow = Aext + ((size_t)(mg & 127) * 1024 + (size_t)(mg >> 7)) * 128;
    } else {
        arow = base + (size_t)(m0 + r) * K;
    }
    const float* wrow = W + (size_t)(n0 + r) * K;

    ull acc[4][2];
#pragma unroll
    for (int i = 0; i < 4; i++) { acc[i][0] = 0ull; acc[i][1] = 0ull; }

    const int nkt = K >> 4;
    float4 av = *(const float4*)(arow + kq * 4);
    float4 wv = *(const float4*)(wrow + kq * 4);

    for (int kt = 0; kt < nkt; kt++) {
        Asd[kq * 4 + 0][r] = pk(av.x, av.x);
        Asd[kq * 4 + 1][r] = pk(av.y, av.y);
        Asd[kq * 4 + 2][r] = pk(av.z, av.z);
        Asd[kq * 4 + 3][r] = pk(av.w, av.w);
        Bs[kq * 4 + 0][r] = wv.x; Bs[kq * 4 + 1][r] = wv.y;
        Bs[kq * 4 + 2][r] = wv.z; Bs[kq * 4 + 3][r] = wv.w;
        __syncthreads();
        if (kt + 1 < nkt) {
            av = *(const float4*)(arow + (kt + 1) * 16 + kq * 4);
            wv = *(const float4*)(wrow + (kt + 1) * 16 + kq * 4);
        }
#pragma unroll
        for (int k = 0; k < 16; k++) {
            ulonglong2 bv  = *(const ulonglong2*)&Bs[k][tx * 4];
            ulonglong2 a01 = *(const ulonglong2*)&Asd[k][ty * 4];
            ulonglong2 a23 = *(const ulonglong2*)&Asd[k][ty * 4 + 2];
            acc[0][0] = f2fma(a01.x, bv.x, acc[0][0]); acc[0][1] = f2fma(a01.x, bv.y, acc[0][1]);
            acc[1][0] = f2fma(a01.y, bv.x, acc[1][0]); acc[1][1] = f2fma(a01.y, bv.y, acc[1][1]);
            acc[2][0] = f2fma(a23.x, bv.x, acc[2][0]); acc[2][1] = f2fma(a23.x, bv.y, acc[2][1]);
            acc[3][0] = f2fma(a23.y, bv.x, acc[3][0]); acc[3][1] = f2fma(a23.y, bv.y, acc[3][1]);
        }
        __syncthreads();
    }

    const int n = n0 + tx * 4;
    float bb[4];
#pragma unroll
    for (int jj = 0; jj < 4; jj++) {
        bb[jj] = b0[n + jj];
        if (b1) bb[jj] += b1[n + jj];
    }
#pragma unroll
    for (int mi = 0; mi < 4; mi++) {
        int m = m0 + ty * 4 + mi;
        float c0, c1, c2, c3;
        unpk(acc[mi][0], c0, c1);
        unpk(acc[mi][1], c2, c3);
        float4 outv = make_float4(c0 + bb[0], c1 + bb[1], c2 + bb[2], c3 + bb[3]);
        float* crow;
        if (csel == 0)      crow = (m < 65536 ? g_gatesA : g_gatesB) + (size_t)(m & 65535) * 4096;
        else if (csel == 1) crow = g_z1 + (size_t)m * 512;
        else                crow = g_z2 + (size_t)m * 256;
        *(float4*)(crow + n) = outv;
    }
}

// ---------------- BN (eval) + ReLU, in place on g_z1/g_z2 ----------------
__global__ void bn_relu(int sel, const float* __restrict__ gg, const float* __restrict__ bb,
                        const float* __restrict__ mm, const float* __restrict__ vv, int N)
{
    int idx = blockIdx.x * blockDim.x + threadIdx.x;
    if (idx < 128 * N) {
        int n = idx % N;
        float* Z = (sel == 1) ? g_z1 : g_z2;
        float x = Z[idx];
        x = (x - mm[n]) * rsqrtf(vv[n] + 1e-5f) * gg[n] + bb[n];
        Z[idx] = fmaxf(x, 0.f);
    }
}

// ---------------- final fc3 ----------------
__global__ void fc3_k(const float* __restrict__ W, const float* __restrict__ bias,
                      float* __restrict__ out)
{
    int n = blockIdx.x;
    int b = threadIdx.x;
    const float* z = g_z2 + b * 256;
    const float* w = W + n * 256;
    float acc = 0.f;
#pragma unroll 8
    for (int k = 0; k < 256; k += 4) {
        float4 zv = *(const float4*)(z + k);
        float4 wv = *(const float4*)(w + k);
        acc += zv.x * wv.x + zv.y * wv.y + zv.z * wv.z + zv.w * wv.w;
    }
    out[b * 28 + n] = acc + bias[n];
}

// ---------------- launch ----------------
extern "C" void kernel_launch(void* const* d_in, const int* in_sizes, int n_in,
                              void* d_out, int out_size)
{
    const float* x = (const float*)d_in[0];
    const float* Wih[3] = {(const float*)d_in[1], (const float*)d_in[5], (const float*)d_in[9]};
    const float* Whh[3] = {(const float*)d_in[2], (const float*)d_in[6], (const float*)d_in[10]};
    const float* bih[3] = {(const float*)d_in[3], (const float*)d_in[7], (const float*)d_in[11]};
    const float* bhh[3] = {(const float*)d_in[4], (const float*)d_in[8], (const float*)d_in[12]};
    const float* fc1_w = (const float*)d_in[13]; const float* fc1_b = (const float*)d_in[14];
    const float* bn1_g = (const float*)d_in[15]; const float* bn1_b = (const float*)d_in[16];
    const float* bn1_m = (const float*)d_in[17]; const float* bn1_v = (const float*)d_in[18];
    const float* fc2_w = (const float*)d_in[19]; const float* fc2_b = (const float*)d_in[20];
    const float* bn2_g = (const float*)d_in[21]; const float* bn2_b = (const float*)d_in[22];
    const float* bn2_m = (const float*)d_in[23]; const float* bn2_v = (const float*)d_in[24];
    const float* fc3_w = (const float*)d_in[25]; const float* fc3_b = (const float*)d_in[26];

    static int attr_done = 0;
    if (!attr_done) {
        cudaFuncSetAttribute(lstm_layer_mma, cudaFuncAttributeMaxDynamicSharedMemorySize,
                             SMEM_MMA);
        cudaFuncSetAttribute(gemm_mma, cudaFuncAttributeMaxDynamicSharedMemorySize,
                             SMEM_GEMM);
        attr_done = 1;
    }

    // layer 0: small K=128 input GEMM stays on f32x2 path
    gemm_tn<<<dim3(64, 2048), 256>>>(x, Wih[0], bih[0], bhh[0], 128, 0, 0);
    lstm_layer_mma<<<128, 256, SMEM_MMA>>>(Whh[0], 0);

    // layers 1,2: bf16-split tensor-core input GEMM
    for (int l = 1; l < 3; l++) {
        wsplit<<<16384, 256>>>(Wih[l]);
        gemm_mma<<<dim3(32, 1024), 256, SMEM_GEMM>>>(bih[l], bhh[l]);
        lstm_layer_mma<<<128, 256, SMEM_MMA>>>(Whh[l], (l == 2) ? 2 : 1);
    }

    // head: final hidden of layer 2 is in g_hT
    gemm_tn<<<dim3(8, 2), 256>>>(nullptr, fc1_w, fc1_b, nullptr, 1024, 3, 1);
    bn_relu<<<256, 256>>>(1, bn1_g, bn1_b, bn1_m, bn1_v, 512);
    gemm_tn<<<dim3(4, 2), 256>>>(nullptr, fc2_w, fc2_b, nullptr, 512, 4, 2);
    bn_relu<<<128, 256>>>(2, bn2_g, bn2_b, bn2_m, bn2_v, 256);
    fc3_k<<<28, 128>>>(fc3_w, fc3_b, (float*)d_out);
}

// round 16
// speedup vs baseline: 3.7621x; 1.7379x over previous
#include <cuda_runtime.h>
#include <cuda_bf16.h>
#include <cstdint>

typedef unsigned long long ull;

// ---------------- device scratch (no allocations allowed) ----------------
__device__ float g_gatesA[(size_t)512 * 128 * 4096]; // t in [0,512)   : [t][b][4H]
__device__ float g_gatesB[(size_t)512 * 128 * 4096]; // t in [512,1024)
__device__ __align__(16) __nv_bfloat16 g_ybhi[(size_t)131072 * 1024]; // y hi [m][k]
__device__ __align__(16) __nv_bfloat16 g_yblo[(size_t)131072 * 1024]; // y lo [m][k]
__device__ __align__(16) __nv_bfloat16 g_wkhi[(size_t)4096 * 1024];   // Wih hi [n][k]
__device__ __align__(16) __nv_bfloat16 g_wklo[(size_t)4096 * 1024];   // Wih lo [n][k]
// h stored directly in mma A-fragment layout:
// u32 word index = ((kt*8 + w)*32 + l)*4 + q ; word = bf16 pair (k even, k odd)
// with m = w*16 + (l>>2) + 8*(q&1), k = kt*16 + 2*(l&3) + 8*(q>>1) + half
__device__ __align__(16) unsigned g_hfhi[2][65536];
__device__ __align__(16) unsigned g_hflo[2][65536];
__device__ float g_hT[128 * 1024];                   // final hidden, [b][h]
__device__ float g_z1[128 * 512];
__device__ float g_z2[128 * 256];

__device__ unsigned g_bar_cnt = 0;
__device__ volatile unsigned g_bar_gen = 0;

// ---------------- helpers ----------------
__device__ __forceinline__ ull pk(float a, float b) {
    ull r; asm("mov.b64 %0,{%1,%2};" : "=l"(r) : "f"(a), "f"(b)); return r;
}
__device__ __forceinline__ void unpk(ull v, float& a, float& b) {
    asm("mov.b64 {%0,%1},%2;" : "=f"(a), "=f"(b) : "l"(v));
}
__device__ __forceinline__ ull f2fma(ull a, ull b, ull c) {
    ull d; asm("fma.rn.f32x2 %0,%1,%2,%3;" : "=l"(d) : "l"(a), "l"(b), "l"(c)); return d;
}
__device__ __forceinline__ float sigm(float x) {
    return __fdividef(1.f, 1.f + __expf(-x));
}
__device__ __forceinline__ float tanh_(float x) {
    return 1.f - __fdividef(2.f, 1.f + __expf(2.f * x));
}

// grid-wide barrier: all 128 blocks co-resident (grid must be 128)
__device__ __forceinline__ void grid_bar() {
    __threadfence();
    __syncthreads();
    if (threadIdx.x == 0) {
        unsigned g = g_bar_gen;
        unsigned a = atomicAdd(&g_bar_cnt, 1u);
        if (a == 127u) {
            g_bar_cnt = 0u;
            __threadfence();
            g_bar_gen = g + 1u;
        } else {
            while (g_bar_gen == g) { __nanosleep(32); }
        }
    }
    __syncthreads();
}

// ---------------- warp MMA primitives ----------------
__device__ __forceinline__ uint32_t s2u(const void* p) {
    uint32_t a;
    asm("{ .reg .u64 t; cvta.to.shared.u64 t, %1; cvt.u32.u64 %0, t; }" : "=r"(a) : "l"(p));
    return a;
}
__device__ __forceinline__ void ldm4(unsigned* r, uint32_t addr) {
    asm volatile("ldmatrix.sync.aligned.m8n8.x4.shared.b16 {%0,%1,%2,%3}, [%4];"
                 : "=r"(r[0]), "=r"(r[1]), "=r"(r[2]), "=r"(r[3]) : "r"(addr));
}
__device__ __forceinline__ void mma16816(float* c, const unsigned* a, unsigned b0, unsigned b1) {
    asm volatile(
        "mma.sync.aligned.m16n8k16.row.col.f32.bf16.bf16.f32 "
        "{%0,%1,%2,%3}, {%4,%5,%6,%7}, {%8,%9}, {%0,%1,%2,%3};"
        : "+f"(c[0]), "+f"(c[1]), "+f"(c[2]), "+f"(c[3])
        : "r"(a[0]), "r"(a[1]), "r"(a[2]), "r"(a[3]), "r"(b0), "r"(b1));
}
__device__ __forceinline__ void cpa16(uint32_t s, const void* g) {
    asm volatile("cp.async.cg.shared.global [%0], [%1], 16;" :: "r"(s), "l"(g) : "memory");
}
#define CP_COMMIT() asm volatile("cp.async.commit_group;" ::: "memory")
#define CP_WAIT(n)  asm volatile("cp.async.wait_group %0;" :: "n"(n) : "memory")

// ================= big input-projection GEMM via bf16-split mma =================
#define SMEM_GEMM 147456
__global__ __launch_bounds__(256, 1) void gemm_mma(const float* __restrict__ b0v,
                                                   const float* __restrict__ b1v)
{
    extern __shared__ char sm[];
    const uint32_t sb = s2u(sm);
    const int tid = threadIdx.x;
    const int w = tid >> 5, l = tid & 31;
    const int wm = w & 3, wn = w >> 2;
    const int n0 = blockIdx.x << 7, m0 = blockIdx.y << 7;

    const int mat = l >> 3;
    const int arow = (l & 7) + ((mat & 1) << 3);
    const int akof = (mat >> 1) << 3;
    const int brow = (l & 7) + ((mat >> 1) << 3);
    const int bkof = (mat & 1) << 3;

    float acc[2][8][4];
#pragma unroll
    for (int i = 0; i < 2; i++)
#pragma unroll
        for (int jn = 0; jn < 8; jn++)
#pragma unroll
            for (int e = 0; e < 4; e++) acc[i][jn][e] = 0.f;

    auto fill = [&](int t, int buf) {
        const int k0 = t << 6;
#pragma unroll
        for (int i = 0; i < 4; i++) {
            int e = tid + (i << 8);
            int row = e >> 3, q = e & 7;
            uint32_t sa = sb + (uint32_t)(buf * 36864 + row * 144 + q * 16);
            cpa16(sa, g_ybhi + (size_t)(m0 + row) * 1024 + k0 + q * 8);
            cpa16(sa + 18432u, g_yblo + (size_t)(m0 + row) * 1024 + k0 + q * 8);
            uint32_t sbb = sb + 73728u + (uint32_t)(buf * 36864 + row * 144 + q * 16);
            cpa16(sbb, g_wkhi + (size_t)(n0 + row) * 1024 + k0 + q * 8);
            cpa16(sbb + 18432u, g_wklo + (size_t)(n0 + row) * 1024 + k0 + q * 8);
        }
    };

    fill(0, 0);
    CP_COMMIT();

    for (int t = 0; t < 16; t++) {
        const int buf = t & 1;
        if (t < 15) {
            fill(t + 1, buf ^ 1);
            CP_COMMIT();
            CP_WAIT(1);
        } else {
            CP_WAIT(0);
        }
        __syncthreads();

#pragma unroll
        for (int ks = 0; ks < 4; ks++) {
            unsigned ah[2][4], al[2][4], bh[4][4], bl[4][4];
#pragma unroll
            for (int mt = 0; mt < 2; mt++) {
                uint32_t aa = sb + (uint32_t)(buf * 36864 +
                              (wm * 32 + mt * 16 + arow) * 144 + akof * 2 + ks * 32);
                ldm4(ah[mt], aa);
                ldm4(al[mt], aa + 18432u);
            }
#pragma unroll
            for (int p = 0; p < 4; p++) {
                uint32_t ba = sb + 73728u + (uint32_t)(buf * 36864 +
                              (wn * 64 + p * 16 + brow) * 144 + bkof * 2 + ks * 32);
                ldm4(bh[p], ba);
                ldm4(bl[p], ba + 18432u);
            }
#pragma unroll
            for (int mt = 0; mt < 2; mt++)
#pragma unroll
                for (int p = 0; p < 4; p++) {
                    mma16816(acc[mt][2 * p],     ah[mt], bh[p][0], bh[p][1]);
                    mma16816(acc[mt][2 * p],     ah[mt], bl[p][0], bl[p][1]);
                    mma16816(acc[mt][2 * p],     al[mt], bh[p][0], bh[p][1]);
                    mma16816(acc[mt][2 * p + 1], ah[mt], bh[p][2], bh[p][3]);
                    mma16816(acc[mt][2 * p + 1], ah[mt], bl[p][2], bl[p][3]);
                    mma16816(acc[mt][2 * p + 1], al[mt], bh[p][2], bh[p][3]);
                }
        }
        __syncthreads();
    }

    float* hbase = (m0 < 65536 ? g_gatesA : g_gatesB);
    const int mh = m0 & 65535;
    const int cbase = n0 + wn * 64 + (l & 3) * 2;
    float bb[8][2];
#pragma unroll
    for (int p = 0; p < 4; p++)
#pragma unroll
        for (int blk = 0; blk < 2; blk++) {
            int col = cbase + p * 16 + blk * 8;
            bb[2 * p + blk][0] = __ldg(b0v + col) + __ldg(b1v + col);
            bb[2 * p + blk][1] = __ldg(b0v + col + 1) + __ldg(b1v + col + 1);
        }
#pragma unroll
    for (int mt = 0; mt < 2; mt++) {
        int r = mh + wm * 32 + mt * 16 + (l >> 2);
        float* rowA = hbase + (size_t)r * 4096;
        float* rowB = rowA + (size_t)8 * 4096;
#pragma unroll
        for (int p = 0; p < 4; p++)
#pragma unroll
            for (int blk = 0; blk < 2; blk++) {
                int col = cbase + p * 16 + blk * 8;
                const float* a4 = acc[mt][2 * p + blk];
                *(float2*)(rowA + col) = make_float2(a4[0] + bb[2 * p + blk][0],
                                                     a4[1] + bb[2 * p + blk][1]);
                *(float2*)(rowB + col) = make_float2(a4[2] + bb[2 * p + blk][0],
                                                     a4[3] + bb[2 * p + blk][1]);
            }
    }
}

// ---------------- Wih fp32 -> bf16 hi/lo pre-convert ----------------
__global__ void wsplit(const float* __restrict__ W) {
    int i = blockIdx.x * 256 + threadIdx.x; // 4M
    float v = W[i];
    __nv_bfloat16 h = __float2bfloat16(v);
    g_wkhi[i] = h;
    g_wklo[i] = __float2bfloat16(v - __bfloat162float(h));
}

// smem layout (bytes) for lstm_layer_mma: W hi/lo only
#define WHI_OFF  0u
#define WLO_OFF  66048u
#define SMEM_MMA 132096

// ---------------- persistent tensor-core (HMMA) LSTM layer ----------------
// grid = 128 blocks (8 j each -> N=32 cols packed n=(jj<<2)|g), 256 threads.
// A fragments come straight from global (g_hfhi/g_hflo) -- no smem staging.
// ysel: 0/1 -> write y bf16 hi/lo, 2 -> no y, write g_hT fp32 at t==1023.
__global__ __launch_bounds__(256, 1) void lstm_layer_mma(const float* __restrict__ Whh, int ysel)
{
    extern __shared__ char smem[];
    const uint32_t sbase = s2u(smem);
    const int tid = threadIdx.x;
    const int w = tid >> 5, l = tid & 31;
    const int tq = l & 3;
    const int r = (w << 4) + (l >> 2);
    const int j0 = blockIdx.x << 3;

    // ---- fill Whh hi/lo slice: w[n][k], identity k (fragments carry true k) ----
    for (int idx = tid; idx < 32768; idx += 256) {
        int n = idx >> 10, k = idx & 1023;
        int jj = n >> 2, g = n & 3;
        float v = Whh[((size_t)((g << 10) | (j0 + jj))) * 1024 + k];
        __nv_bfloat16 hi = __float2bfloat16(v);
        __nv_bfloat16 lo = __float2bfloat16(v - __bfloat162float(hi));
        ((__nv_bfloat16*)(smem + WHI_OFF))[n * 1032 + k] = hi;
        ((__nv_bfloat16*)(smem + WLO_OFF))[n * 1032 + k] = lo;
    }
    __syncthreads();

    const int mat = l >> 3;
    const int brow = (l & 7) + ((mat >> 1) << 3);
    const int bkof = (mat & 1) << 3;
    uint32_t boff[2];
#pragma unroll
    for (int p = 0; p < 2; p++)
        boff[p] = (uint32_t)(((p << 4) + brow) * 2064 + (bkof << 1));

    const int kb = (tq & 1) ? 2 : 0;
    const int sb2 = (tq & 1) ? 0 : 2;
    const int dlt = tq >> 1;

    float ccr[2][2] = {{0.f, 0.f}, {0.f, 0.f}};

    float ga[2][2][4];
#pragma unroll
    for (int m = 0; m < 2; m++) {
        int jj = 2 * (kb + m) + dlt;
#pragma unroll
        for (int rho = 0; rho < 2; rho++) {
            const float* gp = g_gatesA + (size_t)(r + 8 * rho) * 4096 + j0 + jj;
#pragma unroll
            for (int g = 0; g < 4; g++) ga[m][rho][g] = __ldcs(gp + (g << 10));
        }
    }

    const int fbase = w * 32 + l;  // uint4 index offset within a kt slab (8*32)

    for (int t = 0; t < 1024; t++) {
        float acc[4][4];
#pragma unroll
        for (int i = 0; i < 4; i++)
#pragma unroll
            for (int e = 0; e < 4; e++) acc[i][e] = 0.f;

        if (t > 0) {
            const uint4* __restrict__ Fh = (const uint4*)g_hfhi[t & 1];
            const uint4* __restrict__ Fl = (const uint4*)g_hflo[t & 1];

            uint4 pa[2], pb[2];
            pa[0] = __ldcg(Fh + fbase);
            pb[0] = __ldcg(Fl + fbase);
            pa[1] = __ldcg(Fh + 256 + fbase);
            pb[1] = __ldcg(Fl + 256 + fbase);

#pragma unroll 4
            for (int kt = 0; kt < 64; kt++) {
                const int cur = kt & 1;
                unsigned ah[4] = {pa[cur].x, pa[cur].y, pa[cur].z, pa[cur].w};
                unsigned al[4] = {pb[cur].x, pb[cur].y, pb[cur].z, pb[cur].w};
                if (kt < 62) {
                    pa[cur] = __ldcg(Fh + (kt + 2) * 256 + fbase);
                    pb[cur] = __ldcg(Fl + (kt + 2) * 256 + fbase);
                }
                unsigned bh[2][4], bl[2][4];
                const uint32_t kbyte = (uint32_t)kt << 5;
#pragma unroll
                for (int p = 0; p < 2; p++) {
                    ldm4(bh[p], sbase + WHI_OFF + boff[p] + kbyte);
                    ldm4(bl[p], sbase + WLO_OFF + boff[p] + kbyte);
                }
#pragma unroll
                for (int p = 0; p < 2; p++) {
                    mma16816(acc[2 * p],     ah, bh[p][0], bh[p][1]);
                    mma16816(acc[2 * p],     ah, bl[p][0], bl[p][1]);
                    mma16816(acc[2 * p],     al, bh[p][0], bh[p][1]);
                    mma16816(acc[2 * p + 1], ah, bh[p][2], bh[p][3]);
                    mma16816(acc[2 * p + 1], ah, bl[p][2], bl[p][3]);
                    mma16816(acc[2 * p + 1], al, bh[p][2], bh[p][3]);
                }
            }
        }

        float own[2][4], oth[2][4];
#pragma unroll
        for (int m = 0; m < 2; m++)
#pragma unroll
            for (int e = 0; e < 4; e++) {
                own[m][e] = acc[kb + m][e];
                oth[m][e] = __shfl_xor_sync(0xffffffffu, acc[sb2 + m][e], 1);
            }

        float hv[2][2];
#pragma unroll
        for (int m = 0; m < 2; m++) {
#pragma unroll
            for (int rho = 0; rho < 2; rho++) {
                float G0, G1, G2, G3;
                if (!(tq & 1)) {
                    G0 = own[m][2 * rho]; G1 = own[m][2 * rho + 1];
                    G2 = oth[m][2 * rho]; G3 = oth[m][2 * rho + 1];
                } else {
                    G0 = oth[m][2 * rho]; G1 = oth[m][2 * rho + 1];
                    G2 = own[m][2 * rho]; G3 = own[m][2 * rho + 1];
                }
                float xi = ga[m][rho][0] + G0;
                float xf = ga[m][rho][1] + G1;
                float xg = ga[m][rho][2] + G2;
                float xo = ga[m][rho][3] + G3;
                float ii = sigm(xi), ff = sigm(xf), gg = tanh_(xg), oo = sigm(xo);
                ccr[m][rho] = ff * ccr[m][rho] + ii * gg;
                hv[m][rho] = oo * tanh_(ccr[m][rho]);
            }
        }

        // ---- h store directly into A-fragment layout (8 STG.16 per thread) ----
        {
            const int nb = (t & 1) ^ 1;
            unsigned short* Dh = (unsigned short*)g_hfhi[nb];
            unsigned short* Dl = (unsigned short*)g_hflo[nb];
#pragma unroll
            for (int m = 0; m < 2; m++) {
                int k = j0 + 2 * (kb + m) + dlt;
                int kt = k >> 4, kk = k & 15;
#pragma unroll
                for (int rho = 0; rho < 2; rho++) {
                    int b = r + 8 * rho;
                    int wc = b >> 4, rm = b & 15;
                    int lc = ((rm & 7) << 2) | ((kk >> 1) & 3);
                    int q = ((kk >> 3) << 1) | (rm >> 3);
                    size_t a16 = ((size_t)(((kt * 8 + wc) * 32 + lc) * 4 + q) << 1) | (kk & 1);
                    float v = hv[m][rho];
                    __nv_bfloat16 hh = __float2bfloat16(v);
                    __nv_bfloat16 ll = __float2bfloat16(v - __bfloat162float(hh));
                    Dh[a16] = __bfloat16_as_ushort(hh);
                    Dl[a16] = __bfloat16_as_ushort(ll);
                }
            }
        }
        // ---- y store as bf16 hi/lo (original jj layout), or hT fp32 ----
        if (ysel != 2) {
#pragma unroll
            for (int m = 0; m < 2; m++) {
                int jj = 2 * (kb + m) + dlt;
#pragma unroll
                for (int rho = 0; rho < 2; rho++) {
                    float v = hv[m][rho];
                    __nv_bfloat16 hh = __float2bfloat16(v);
                    __nv_bfloat16 ll = __float2bfloat16(v - __bfloat162float(hh));
                    size_t off = ((size_t)t * 128 + r + 8 * rho) * 1024 + j0 + jj;
                    g_ybhi[off] = hh;
                    g_yblo[off] = ll;
                }
            }
        } else if (t == 1023) {
#pragma unroll
            for (int m = 0; m < 2; m++) {
                int jj = 2 * (kb + m) + dlt;
#pragma unroll
                for (int rho = 0; rho < 2; rho++)
                    g_hT[(size_t)(r + 8 * rho) * 1024 + j0 + jj] = hv[m][rho];
            }
        }

        float gan[2][2][4];
        if (t < 1023) {
            const float* gpb = (t + 1 < 512 ? g_gatesA : g_gatesB)
                               + (size_t)((t + 1) & 511) * (128 * 4096);
#pragma unroll
            for (int m = 0; m < 2; m++) {
                int jj = 2 * (kb + m) + dlt;
#pragma unroll
                for (int rho = 0; rho < 2; rho++) {
                    const float* gp = gpb + (size_t)(r + 8 * rho) * 4096 + j0 + jj;
#pragma unroll
                    for (int g = 0; g < 4; g++) gan[m][rho][g] = __ldcs(gp + (g << 10));
                }
            }
        }

        grid_bar();

#pragma unroll
        for (int m = 0; m < 2; m++)
#pragma unroll
            for (int rho = 0; rho < 2; rho++)
#pragma unroll
                for (int g = 0; g < 4; g++) ga[m][rho][g] = gan[m][rho][g];
    }
}

// ---------------- generic C = A @ W^T + b0 (+b1), tiled 64x64x16, f32x2 ----------------
// asel: 0 = Aext layer0 x mapping; 3 = g_hT; 4 = g_z1
// csel: 0 = gates, 1 = g_z1, 2 = g_z2
__global__ __launch_bounds__(256) void gemm_tn(
    const float* __restrict__ Aext, const float* __restrict__ W,
    const float* __restrict__ b0, const float* __restrict__ b1,
    int K, int asel, int csel)
{
    __shared__ ull   Asd[16][66];
    __shared__ float Bs[16][68];
    const int tid = threadIdx.x;
    const int tx = tid & 15, ty = tid >> 4;
    const int m0 = blockIdx.y * 64, n0 = blockIdx.x * 64;

    const float* base = Aext;
    if (asel == 3) base = g_hT;
    else if (asel == 4) base = g_z1;

    const int r = tid >> 2, kq = tid & 3;
    const float* arow;
    if (asel == 0) {
        int mg = m0 + r;
        arow = Aext + ((size_t)(mg & 127) * 1024 + (size_t)(mg >> 7)) * 128;
    } else {
        arow = base + (size_t)(m0 + r) * K;
    }
    const float* wrow = W + (size_t)(n0 + r) * K;

    ull acc[4][2];
#pragma unroll
    for (int i = 0; i < 4; i++) { acc[i][0] = 0ull; acc[i][1] = 0ull; }

    const int nkt = K >> 4;
    float4 av = *(const float4*)(arow + kq * 4);
    float4 wv = *(const float4*)(wrow + kq * 4);

    for (int kt = 0; kt < nkt; kt++) {
        Asd[kq * 4 + 0][r] = pk(av.x, av.x);
        Asd[kq * 4 + 1][r] = pk(av.y, av.y);
        Asd[kq * 4 + 2][r] = pk(av.z, av.z);
        Asd[kq * 4 + 3][r] = pk(av.w, av.w);
        Bs[kq * 4 + 0][r] = wv.x; Bs[kq * 4 + 1][r] = wv.y;
        Bs[kq * 4 + 2][r] = wv.z; Bs[kq * 4 + 3][r] = wv.w;
        __syncthreads();
        if (kt + 1 < nkt) {
            av = *(const float4*)(arow + (kt + 1) * 16 + kq * 4);
            wv = *(const float4*)(wrow + (kt + 1) * 16 + kq * 4);
        }
#pragma unroll
        for (int k = 0; k < 16; k++) {
            ulonglong2 bv  = *(const ulonglong2*)&Bs[k][tx * 4];
            ulonglong2 a01 = *(const ulonglong2*)&Asd[k][ty * 4];
            ulonglong2 a23 = *(const ulonglong2*)&Asd[k][ty * 4 + 2];
            acc[0][0] = f2fma(a01.x, bv.x, acc[0][0]); acc[0][1] = f2fma(a01.x, bv.y, acc[0][1]);
            acc[1][0] = f2fma(a01.y, bv.x, acc[1][0]); acc[1][1] = f2fma(a01.y, bv.y, acc[1][1]);
            acc[2][0] = f2fma(a23.x, bv.x, acc[2][0]); acc[2][1] = f2fma(a23.x, bv.y, acc[2][1]);
            acc[3][0] = f2fma(a23.y, bv.x, acc[3][0]); acc[3][1] = f2fma(a23.y, bv.y, acc[3][1]);
        }
        __syncthreads();
    }

    const int n = n0 + tx * 4;
    float bb[4];
#pragma unroll
    for (int jj = 0; jj < 4; jj++) {
        bb[jj] = b0[n + jj];
        if (b1) bb[jj] += b1[n + jj];
    }
#pragma unroll
    for (int mi = 0; mi < 4; mi++) {
        int m = m0 + ty * 4 + mi;
        float c0, c1, c2, c3;
        unpk(acc[mi][0], c0, c1);
        unpk(acc[mi][1], c2, c3);
        float4 outv = make_float4(c0 + bb[0], c1 + bb[1], c2 + bb[2], c3 + bb[3]);
        float* crow;
        if (csel == 0)      crow = (m < 65536 ? g_gatesA : g_gatesB) + (size_t)(m & 65535) * 4096;
        else if (csel == 1) crow = g_z1 + (size_t)m * 512;
        else                crow = g_z2 + (size_t)m * 256;
        *(float4*)(crow + n) = outv;
    }
}

// ---------------- BN (eval) + ReLU, in place on g_z1/g_z2 ----------------
__global__ void bn_relu(int sel, const float* __restrict__ gg, const float* __restrict__ bb,
                        const float* __restrict__ mm, const float* __restrict__ vv, int N)
{
    int idx = blockIdx.x * blockDim.x + threadIdx.x;
    if (idx < 128 * N) {
        int n = idx % N;
        float* Z = (sel == 1) ? g_z1 : g_z2;
        float x = Z[idx];
        x = (x - mm[n]) * rsqrtf(vv[n] + 1e-5f) * gg[n] + bb[n];
        Z[idx] = fmaxf(x, 0.f);
    }
}

// ---------------- final fc3 ----------------
__global__ void fc3_k(const float* __restrict__ W, const float* __restrict__ bias,
                      float* __restrict__ out)
{
    int n = blockIdx.x;
    int b = threadIdx.x;
    const float* z = g_z2 + b * 256;
    const float* w = W + n * 256;
    float acc = 0.f;
#pragma unroll 8
    for (int k = 0; k < 256; k += 4) {
        float4 zv = *(const float4*)(z + k);
        float4 wv = *(const float4*)(w + k);
        acc += zv.x * wv.x + zv.y * wv.y + zv.z * wv.z + zv.w * wv.w;
    }
    out[b * 28 + n] = acc + bias[n];
}

// ---------------- launch ----------------
extern "C" void kernel_launch(void* const* d_in, const int* in_sizes, int n_in,
                              void* d_out, int out_size)
{
    const float* x = (const float*)d_in[0];
    const float* Wih[3] = {(const float*)d_in[1], (const float*)d_in[5], (const float*)d_in[9]};
    const float* Whh[3] = {(const float*)d_in[2], (const float*)d_in[6], (const float*)d_in[10]};
    const float* bih[3] = {(const float*)d_in[3], (const float*)d_in[7], (const float*)d_in[11]};
    const float* bhh[3] = {(const float*)d_in[4], (const float*)d_in[8], (const float*)d_in[12]};
    const float* fc1_w = (const float*)d_in[13]; const float* fc1_b = (const float*)d_in[14];
    const float* bn1_g = (const float*)d_in[15]; const float* bn1_b = (const float*)d_in[16];
    const float* bn1_m = (const float*)d_in[17]; const float* bn1_v = (const float*)d_in[18];
    const float* fc2_w = (const float*)d_in[19]; const float* fc2_b = (const float*)d_in[20];
    const float* bn2_g = (const float*)d_in[21]; const float* bn2_b = (const float*)d_in[22];
    const float* bn2_m = (const float*)d_in[23]; const float* bn2_v = (const float*)d_in[24];
    const float* fc3_w = (const float*)d_in[25]; const float* fc3_b = (const float*)d_in[26];

    static int attr_done = 0;
    if (!attr_done) {
        cudaFuncSetAttribute(lstm_layer_mma, cudaFuncAttributeMaxDynamicSharedMemorySize,
                             SMEM_MMA);
        cudaFuncSetAttribute(gemm_mma, cudaFuncAttributeMaxDynamicSharedMemorySize,
                             SMEM_GEMM);
        attr_done = 1;
    }

    // layer 0: small K=128 input GEMM stays on f32x2 path
    gemm_tn<<<dim3(64, 2048), 256>>>(x, Wih[0], bih[0], bhh[0], 128, 0, 0);
    lstm_layer_mma<<<128, 256, SMEM_MMA>>>(Whh[0], 0);

    // layers 1,2: bf16-split tensor-core input GEMM
    for (int l = 1; l < 3; l++) {
        wsplit<<<16384, 256>>>(Wih[l]);
        gemm_mma<<<dim3(32, 1024), 256, SMEM_GEMM>>>(bih[l], bhh[l]);
        lstm_layer_mma<<<128, 256, SMEM_MMA>>>(Whh[l], (l == 2) ? 2 : 1);
    }

    // head: final hidden of layer 2 is in g_hT
    gemm_tn<<<dim3(8, 2), 256>>>(nullptr, fc1_w, fc1_b, nullptr, 1024, 3, 1);
    bn_relu<<<256, 256>>>(1, bn1_g, bn1_b, bn1_m, bn1_v, 512);
    gemm_tn<<<dim3(4, 2), 256>>>(nullptr, fc2_w, fc2_b, nullptr, 512, 4, 2);
    bn_relu<<<128, 256>>>(2, bn2_g, bn2_b, bn2_m, bn2_v, 256);
    fc3_k<<<28, 128>>>(fc3_w, fc3_b, (float*)d_out);
}